// round 4
// baseline (speedup 1.0000x reference)
#include <cuda_runtime.h>

// KAN 3x3 convolution, uniform cubic B-spline closed form.
// x: (32, 256, 256) f32 in [0,1), base_weight: (3,3), spline_weight: (3,3,8)
// out: (32, 254, 254) f32
//
// Strategy: spline weights register-resident (only basis columns 2..7
// reachable for x in [0,1)), dense 6-vector basis expansion per pixel via
// selects -> pure FFMA accumulation, no shared memory in the hot loop.
// Output stored as 2x float2 (row base oh*254 + oc0 is always 8B-aligned;
// float4 would trap on odd rows since 254 % 4 != 0).

namespace {
constexpr int H  = 256, W  = 256;
constexpr int Ho = 254, Wo = 254;
constexpr int NB = 8;          // GRID_SIZE + SPLINE_ORDER
constexpr int TW = 4, TH = 4;  // per-thread output tile
constexpr int BTX = 32, BTY = 8;  // 256 threads; block covers 128x32 outputs
}

__global__ __launch_bounds__(BTX * BTY, 2)
void kan_conv_kernel(const float* __restrict__ x,
                     const float* __restrict__ bw,
                     const float* __restrict__ sw,
                     float* __restrict__ out)
{
    // Register-resident weights: swr[p][k] = sw[p][2+k], k=0..5 (reachable cols).
    float swr[9][6], bwr[9];
#pragma unroll
    for (int p = 0; p < 9; ++p) {
#pragma unroll
        for (int k = 0; k < 6; ++k) swr[p][k] = __ldg(&sw[p * NB + 2 + k]);
        bwr[p] = __ldg(&bw[p]);
    }

    const int batch = blockIdx.z;
    const int oc0 = (blockIdx.x * BTX + threadIdx.x) * TW;
    const int or0 = (blockIdx.y * BTY + threadIdx.y) * TH;
    const float* __restrict__ xb = x + batch * H * W;

    float acc[TH][TW];
#pragma unroll
    for (int i = 0; i < TH; ++i)
#pragma unroll
        for (int j = 0; j < TW; ++j) acc[i][j] = 0.0f;

    const bool fastcols = (oc0 + TW + 2 <= W);   // vector loads fully in-row

#pragma unroll
    for (int r = 0; r < TH + 2; ++r) {
        const int ir = min(or0 + r, H - 1);
        const float* __restrict__ xrow = xb + ir * W;

        // Load the 6 pixels for this row (vectorized when safely in-bounds;
        // x row base is 256 floats so oc0 (mult of 4) keeps 16B alignment).
        float px[TW + 2];
        if (fastcols) {
            const float4 v4 = *reinterpret_cast<const float4*>(xrow + oc0);
            const float2 v2 = *reinterpret_cast<const float2*>(xrow + oc0 + 4);
            px[0] = v4.x; px[1] = v4.y; px[2] = v4.z; px[3] = v4.w;
            px[4] = v2.x; px[5] = v2.y;
        } else {
#pragma unroll
            for (int cc = 0; cc < TW + 2; ++cc)
                px[cc] = __ldg(&xrow[min(oc0 + cc, W - 1)]);
        }

#pragma unroll
        for (int cc = 0; cc < TW + 2; ++cc) {
            const float xv = px[cc];

            // --- per-pixel transform ---
            // grid[i] = (i-3)*0.4 - 1  =>  scaled = x*2.5 + 5.5  in [5.5, 8)
            float scaled = fmaf(xv, 2.5f, 5.5f);
            float fi = floorf(scaled);
            fi = fminf(fmaxf(fi, 5.0f), 7.0f);
            const float t  = scaled - fi;
            const int   o  = (int)fi - 5;         // 0..2
            const float t2 = t * t;
            const float u  = 1.0f - t;
            const float w0 = u * u * u * (1.0f / 6.0f);
            const float w3 = t2 * t * (1.0f / 6.0f);
            const float w1 = fmaf(t2, fmaf(0.5f, t, -1.0f), 2.0f / 3.0f);
            const float w2 = 1.0f - w0 - w1 - w3;     // partition of unity

            // Dense 6-vector basis: g[o + j] = w_j, else 0.
            const bool o0 = (o == 0), o1 = (o == 1), o2 = (o == 2);
            float g[6];
            g[0] = o0 ? w0 : 0.0f;
            g[1] = o0 ? w1 : (o1 ? w0 : 0.0f);
            g[2] = o0 ? w2 : (o1 ? w1 : w0);
            g[3] = o0 ? w3 : (o1 ? w2 : w1);
            g[4] = o1 ? w3 : (o2 ? w2 : 0.0f);
            g[5] = o2 ? w3 : 0.0f;

            const float e = __expf(-xv);
            const float s = __fdividef(xv, 1.0f + e);  // silu(x)

            // --- accumulate into affected outputs: pure FFMA chains ---
#pragma unroll
            for (int orr = 0; orr < TH; ++orr) {
                const int a = r - orr;
                if (a < 0 || a > 2) continue;
#pragma unroll
                for (int occ = 0; occ < TW; ++occ) {
                    const int b = cc - occ;
                    if (b < 0 || b > 2) continue;
                    const int p = a * 3 + b;
                    float v = fmaf(s, bwr[p], acc[orr][occ]);
                    v = fmaf(g[5], swr[p][5], v);
                    v = fmaf(g[4], swr[p][4], v);
                    v = fmaf(g[3], swr[p][3], v);
                    v = fmaf(g[2], swr[p][2], v);
                    v = fmaf(g[1], swr[p][1], v);
                    v = fmaf(g[0], swr[p][0], v);
                    acc[orr][occ] = v;
                }
            }
        }
    }

    float* __restrict__ ob = out + batch * Ho * Wo;
#pragma unroll
    for (int orr = 0; orr < TH; ++orr) {
        const int oh = or0 + orr;
        if (oh >= Ho) continue;
        if (oc0 + TW <= Wo) {
            // oh*Wo + oc0 is even (Wo=254 even, oc0 mult of 4) -> 8B aligned.
            float* rowp = ob + oh * Wo + oc0;
            *reinterpret_cast<float2*>(rowp)     = make_float2(acc[orr][0], acc[orr][1]);
            *reinterpret_cast<float2*>(rowp + 2) = make_float2(acc[orr][2], acc[orr][3]);
        } else {
#pragma unroll
            for (int occ = 0; occ < TW; ++occ) {
                const int ow = oc0 + occ;
                if (ow < Wo) ob[oh * Wo + ow] = acc[orr][occ];
            }
        }
    }
}

extern "C" void kernel_launch(void* const* d_in, const int* in_sizes, int n_in,
                              void* d_out, int out_size)
{
    const float* x  = (const float*)d_in[0];
    const float* bw = (const float*)d_in[1];
    const float* sw = (const float*)d_in[2];
    float* out = (float*)d_out;

    dim3 block(BTX, BTY);
    dim3 grid((Wo + BTX * TW - 1) / (BTX * TW),   // 2
              (Ho + BTY * TH - 1) / (BTY * TH),   // 8
              32);
    kan_conv_kernel<<<grid, block>>>(x, bw, sw, out);
}

// round 5
// speedup vs baseline: 1.0152x; 1.0152x over previous
#include <cuda_runtime.h>

// KAN 3x3 convolution, truncated-power cubic form + FFMA2 (f32x2) packing.
// x: (32, 256, 256) f32 in [0,1), base_weight: (3,3), spline_weight: (3,3,8)
// out: (32, 254, 254) f32
//
// For x in [0,1) the uniform cubic B-spline mixture per tap p equals
//   c0 + c1 x + c2 x^2 + c3 x^3 + d1 relu(x-0.2)^3 + d2 relu(x-0.6)^3
// so each (output, tap) contribution is a 7-term dot with the per-pixel
// feature phi = (1, x, x^2, x^3, R1, R2, silu(x)). phi and coefficients are
// packed into float2 lanes and accumulated with fma.rn.f32x2 (FFMA2):
// 4 packed FMAs per tap instead of 7 scalar FMAs, no interval selects.

namespace {
constexpr int H  = 256, W  = 256;
constexpr int Ho = 254, Wo = 254;
constexpr int NB = 8;          // GRID_SIZE + SPLINE_ORDER
constexpr int TW = 4, TH = 4;  // per-thread output tile
constexpr int BTX = 32, BTY = 8;  // 256 threads; block covers 128x32 outputs
}

typedef unsigned long long u64;

__device__ __forceinline__ u64 pk2(float lo, float hi) {
    u64 r;
    asm("mov.b64 %0, {%1, %2};" : "=l"(r) : "f"(lo), "f"(hi));
    return r;
}
__device__ __forceinline__ void fma2(u64& acc, u64 a, u64 b) {
    asm("fma.rn.f32x2 %0, %1, %2, %3;" : "=l"(acc) : "l"(a), "l"(b), "l"(acc));
}
__device__ __forceinline__ float hadd2(u64 v) {
    float lo, hi;
    asm("mov.b64 {%0, %1}, %2;" : "=f"(lo), "=f"(hi) : "l"(v));
    return lo + hi;
}

__global__ __launch_bounds__(BTX * BTY, 2)
void kan_conv_kernel(const float* __restrict__ x,
                     const float* __restrict__ bw,
                     const float* __restrict__ sw,
                     float* __restrict__ out)
{
    // ---- prologue: derive truncated-power coefficients per tap ----
    // Piece o (x in [0.2o-0.2+eps window)): S_o(t) = A+Bt+Ct^2+Dt^3,
    // t = 2.5x + (0.5 - o). Piece 0 expanded in x gives c0..c3; knot jumps
    // give d1, d2 via third-derivative deltas.
    u64 th2[9][4];   // packed (c0,c1)(c2,c3)(d1,d2)(bw,0) per tap
#pragma unroll
    for (int p = 0; p < 9; ++p) {
        float s_[6];
#pragma unroll
        for (int k = 0; k < 6; ++k) s_[k] = __ldg(&sw[p * NB + 2 + k]);
        const float bwp = __ldg(&bw[p]);

        const float D0 = (-s_[0] + 3.0f * s_[1] - 3.0f * s_[2] + s_[3]) * (1.0f / 6.0f);
        const float D1 = (-s_[1] + 3.0f * s_[2] - 3.0f * s_[3] + s_[4]) * (1.0f / 6.0f);
        const float D2 = (-s_[2] + 3.0f * s_[3] - 3.0f * s_[4] + s_[5]) * (1.0f / 6.0f);
        const float A  = (s_[0] + 4.0f * s_[1] + s_[2]) * (1.0f / 6.0f);
        const float B  = (s_[2] - s_[0]) * 0.5f;
        const float C  = (s_[0] - 2.0f * s_[1] + s_[2]) * 0.5f;

        const float c0 = A + 0.5f * B + 0.25f * C + 0.125f * D0;
        const float c1 = 2.5f * B + 2.5f * C + 1.875f * D0;
        const float c2 = 6.25f * C + 9.375f * D0;
        const float c3 = 15.625f * D0;
        const float d1 = 15.625f * (D1 - D0);
        const float d2 = 15.625f * (D2 - D1);

        th2[p][0] = pk2(c0, c1);
        th2[p][1] = pk2(c2, c3);
        th2[p][2] = pk2(d1, d2);
        th2[p][3] = pk2(bwp, 0.0f);
    }

    const int batch = blockIdx.z;
    const int oc0 = (blockIdx.x * BTX + threadIdx.x) * TW;
    const int or0 = (blockIdx.y * BTY + threadIdx.y) * TH;
    const float* __restrict__ xb = x + batch * H * W;

    u64 acc[TH][TW];   // packed even/odd-k partial sums per output
#pragma unroll
    for (int i = 0; i < TH; ++i)
#pragma unroll
        for (int j = 0; j < TW; ++j) acc[i][j] = 0ULL;

    const bool fastcols = (oc0 + TW + 2 <= W);   // vector loads fully in-row

#pragma unroll
    for (int r = 0; r < TH + 2; ++r) {
        const int ir = min(or0 + r, H - 1);
        const float* __restrict__ xrow = xb + ir * W;

        float px[TW + 2];
        if (fastcols) {
            const float4 v4 = *reinterpret_cast<const float4*>(xrow + oc0);
            const float2 v2 = *reinterpret_cast<const float2*>(xrow + oc0 + 4);
            px[0] = v4.x; px[1] = v4.y; px[2] = v4.z; px[3] = v4.w;
            px[4] = v2.x; px[5] = v2.y;
        } else {
#pragma unroll
            for (int cc = 0; cc < TW + 2; ++cc)
                px[cc] = __ldg(&xrow[min(oc0 + cc, W - 1)]);
        }

#pragma unroll
        for (int cc = 0; cc < TW + 2; ++cc) {
            const float xv = px[cc];

            // --- per-pixel feature phi (no interval logic) ---
            const float x2 = xv * xv;
            const float x3 = x2 * xv;
            const float r1 = fmaxf(xv - 0.2f, 0.0f);
            const float r2 = fmaxf(xv - 0.6f, 0.0f);
            const float R1 = r1 * r1 * r1;
            const float R2 = r2 * r2 * r2;
            const float e  = __expf(-xv);
            const float s  = __fdividef(xv, 1.0f + e);  // silu(x)

            const u64 f0 = pk2(1.0f, xv);
            const u64 f1 = pk2(x2, x3);
            const u64 f2 = pk2(R1, R2);
            const u64 f3 = pk2(s, 0.0f);

            // --- accumulate: 4 FFMA2 per (output, tap) ---
#pragma unroll
            for (int orr = 0; orr < TH; ++orr) {
                const int a = r - orr;
                if (a < 0 || a > 2) continue;
#pragma unroll
                for (int occ = 0; occ < TW; ++occ) {
                    const int b = cc - occ;
                    if (b < 0 || b > 2) continue;
                    const int p = a * 3 + b;
                    fma2(acc[orr][occ], f0, th2[p][0]);
                    fma2(acc[orr][occ], f1, th2[p][1]);
                    fma2(acc[orr][occ], f2, th2[p][2]);
                    fma2(acc[orr][occ], f3, th2[p][3]);
                }
            }
        }
    }

    float* __restrict__ ob = out + batch * Ho * Wo;
#pragma unroll
    for (int orr = 0; orr < TH; ++orr) {
        const int oh = or0 + orr;
        if (oh >= Ho) continue;
        float res[TW];
#pragma unroll
        for (int occ = 0; occ < TW; ++occ) res[occ] = hadd2(acc[orr][occ]);

        if (oc0 + TW <= Wo) {
            // oh*Wo + oc0 is even (Wo=254 even, oc0 mult of 4) -> 8B aligned.
            float* rowp = ob + oh * Wo + oc0;
            *reinterpret_cast<float2*>(rowp)     = make_float2(res[0], res[1]);
            *reinterpret_cast<float2*>(rowp + 2) = make_float2(res[2], res[3]);
        } else {
#pragma unroll
            for (int occ = 0; occ < TW; ++occ) {
                const int ow = oc0 + occ;
                if (ow < Wo) ob[oh * Wo + ow] = res[occ];
            }
        }
    }
}

extern "C" void kernel_launch(void* const* d_in, const int* in_sizes, int n_in,
                              void* d_out, int out_size)
{
    const float* x  = (const float*)d_in[0];
    const float* bw = (const float*)d_in[1];
    const float* sw = (const float*)d_in[2];
    float* out = (float*)d_out;

    dim3 block(BTX, BTY);
    dim3 grid((Wo + BTX * TW - 1) / (BTX * TW),   // 2
              (Ho + BTY * TH - 1) / (BTY * TH),   // 8
              32);
    kan_conv_kernel<<<grid, block>>>(x, bw, sw, out);
}

// round 6
// speedup vs baseline: 1.1194x; 1.1026x over previous
#include <cuda_runtime.h>

// KAN 3x3 convolution, truncated-power cubic form + FFMA2 (f32x2) packing.
// x: (32, 256, 256) f32 in [0,1), base_weight: (3,3), spline_weight: (3,3,8)
// out: (32, 254, 254) f32
//
// For x in [0,1): spline_p(x) = c0 + c1 x + c2 x^2 + c3 x^3
//                              + d1 relu(x-0.2)^3 + d2 relu(x-0.6)^3.
// Since every output sums all 9 taps, the c0 terms collapse to one constant
// C* added at accumulator init. Remaining 6 terms + silu*bw pack into
// 3 fma.rn.f32x2 per (output, tap): (x,x2)(x3,R1)(R2,s) . (c1,c2)(c3,d1)(d2,bw).
// Accumulators use "+l" in-place asm constraints (no MOV-pair shuffles).

namespace {
constexpr int H  = 256, W  = 256;
constexpr int Ho = 254, Wo = 254;
constexpr int NB = 8;          // GRID_SIZE + SPLINE_ORDER
constexpr int TW = 4, TH = 4;  // per-thread output tile
constexpr int BTX = 32, BTY = 8;  // 256 threads; block covers 128x32 outputs
}

typedef unsigned long long u64;

__device__ __forceinline__ u64 pk2(float lo, float hi) {
    u64 r;
    asm("mov.b64 %0, {%1, %2};" : "=l"(r) : "f"(lo), "f"(hi));
    return r;
}
__device__ __forceinline__ void fma2(u64& acc, u64 a, u64 b) {
    asm("fma.rn.f32x2 %0, %1, %2, %0;" : "+l"(acc) : "l"(a), "l"(b));
}
__device__ __forceinline__ float hadd2(u64 v) {
    float lo, hi;
    asm("mov.b64 {%0, %1}, %2;" : "=f"(lo), "=f"(hi) : "l"(v));
    return lo + hi;
}

__global__ __launch_bounds__(BTX * BTY, 2)
void kan_conv_kernel(const float* __restrict__ x,
                     const float* __restrict__ bw,
                     const float* __restrict__ sw,
                     float* __restrict__ out)
{
    // ---- prologue: truncated-power coefficients per tap ----
    u64 th2[9][3];      // packed (c1,c2)(c3,d1)(d2,bw) per tap
    float cstar = 0.0f; // sum of c0 over all taps
#pragma unroll
    for (int p = 0; p < 9; ++p) {
        float s_[6];
#pragma unroll
        for (int k = 0; k < 6; ++k) s_[k] = __ldg(&sw[p * NB + 2 + k]);
        const float bwp = __ldg(&bw[p]);

        const float D0 = (-s_[0] + 3.0f * s_[1] - 3.0f * s_[2] + s_[3]) * (1.0f / 6.0f);
        const float D1 = (-s_[1] + 3.0f * s_[2] - 3.0f * s_[3] + s_[4]) * (1.0f / 6.0f);
        const float D2 = (-s_[2] + 3.0f * s_[3] - 3.0f * s_[4] + s_[5]) * (1.0f / 6.0f);
        const float A  = (s_[0] + 4.0f * s_[1] + s_[2]) * (1.0f / 6.0f);
        const float B  = (s_[2] - s_[0]) * 0.5f;
        const float C  = (s_[0] - 2.0f * s_[1] + s_[2]) * 0.5f;

        const float c0 = A + 0.5f * B + 0.25f * C + 0.125f * D0;
        const float c1 = 2.5f * B + 2.5f * C + 1.875f * D0;
        const float c2 = 6.25f * C + 9.375f * D0;
        const float c3 = 15.625f * D0;
        const float d1 = 15.625f * (D1 - D0);
        const float d2 = 15.625f * (D2 - D1);

        cstar += c0;
        th2[p][0] = pk2(c1, c2);
        th2[p][1] = pk2(c3, d1);
        th2[p][2] = pk2(d2, bwp);
    }
    const u64 acc_init = pk2(cstar, 0.0f);

    const int batch = blockIdx.z;
    const int oc0 = (blockIdx.x * BTX + threadIdx.x) * TW;
    const int or0 = (blockIdx.y * BTY + threadIdx.y) * TH;
    const float* __restrict__ xb = x + batch * H * W;

    u64 acc[TH][TW];   // packed partial sums per output (final = lo + hi)
#pragma unroll
    for (int i = 0; i < TH; ++i)
#pragma unroll
        for (int j = 0; j < TW; ++j) acc[i][j] = acc_init;

    const bool fastcols = (oc0 + TW + 2 <= W);   // vector loads fully in-row

#pragma unroll
    for (int r = 0; r < TH + 2; ++r) {
        const int ir = min(or0 + r, H - 1);
        const float* __restrict__ xrow = xb + ir * W;

        float px[TW + 2];
        if (fastcols) {
            const float4 v4 = *reinterpret_cast<const float4*>(xrow + oc0);
            const float2 v2 = *reinterpret_cast<const float2*>(xrow + oc0 + 4);
            px[0] = v4.x; px[1] = v4.y; px[2] = v4.z; px[3] = v4.w;
            px[4] = v2.x; px[5] = v2.y;
        } else {
#pragma unroll
            for (int cc = 0; cc < TW + 2; ++cc)
                px[cc] = __ldg(&xrow[min(oc0 + cc, W - 1)]);
        }

#pragma unroll
        for (int cc = 0; cc < TW + 2; ++cc) {
            const float xv = px[cc];

            // --- per-pixel feature (no interval logic) ---
            const float x2 = xv * xv;
            const float x3 = x2 * xv;
            const float r1 = fmaxf(xv - 0.2f, 0.0f);
            const float r2 = fmaxf(xv - 0.6f, 0.0f);
            const float R1 = r1 * r1 * r1;
            const float R2 = r2 * r2 * r2;
            const float e  = __expf(-xv);
            const float s  = __fdividef(xv, 1.0f + e);  // silu(x)

            const u64 f0 = pk2(xv, x2);
            const u64 f1 = pk2(x3, R1);
            const u64 f2 = pk2(R2, s);

            // --- accumulate: 3 FFMA2 per (output, tap) ---
#pragma unroll
            for (int orr = 0; orr < TH; ++orr) {
                const int a = r - orr;
                if (a < 0 || a > 2) continue;
#pragma unroll
                for (int occ = 0; occ < TW; ++occ) {
                    const int b = cc - occ;
                    if (b < 0 || b > 2) continue;
                    const int p = a * 3 + b;
                    fma2(acc[orr][occ], f0, th2[p][0]);
                    fma2(acc[orr][occ], f1, th2[p][1]);
                    fma2(acc[orr][occ], f2, th2[p][2]);
                }
            }
        }
    }

    float* __restrict__ ob = out + batch * Ho * Wo;
#pragma unroll
    for (int orr = 0; orr < TH; ++orr) {
        const int oh = or0 + orr;
        if (oh >= Ho) continue;
        float res[TW];
#pragma unroll
        for (int occ = 0; occ < TW; ++occ) res[occ] = hadd2(acc[orr][occ]);

        if (oc0 + TW <= Wo) {
            // oh*Wo + oc0 is even (Wo=254 even, oc0 mult of 4) -> 8B aligned.
            float* rowp = ob + oh * Wo + oc0;
            *reinterpret_cast<float2*>(rowp)     = make_float2(res[0], res[1]);
            *reinterpret_cast<float2*>(rowp + 2) = make_float2(res[2], res[3]);
        } else {
#pragma unroll
            for (int occ = 0; occ < TW; ++occ) {
                const int ow = oc0 + occ;
                if (ow < Wo) ob[oh * Wo + ow] = res[occ];
            }
        }
    }
}

extern "C" void kernel_launch(void* const* d_in, const int* in_sizes, int n_in,
                              void* d_out, int out_size)
{
    const float* x  = (const float*)d_in[0];
    const float* bw = (const float*)d_in[1];
    const float* sw = (const float*)d_in[2];
    float* out = (float*)d_out;

    dim3 block(BTX, BTY);
    dim3 grid((Wo + BTX * TW - 1) / (BTX * TW),   // 2
              (Ho + BTY * TH - 1) / (BTY * TH),   // 8
              32);
    kan_conv_kernel<<<grid, block>>>(x, bw, sw, out);
}

// round 7
// speedup vs baseline: 1.1385x; 1.0171x over previous
#include <cuda_runtime.h>

// KAN 3x3 convolution, truncated-power cubic form, pure scalar FFMA.
// x: (32, 256, 256) f32 in [0,1), base_weight: (3,3), spline_weight: (3,3,8)
// out: (32, 254, 254) f32
//
// For x in [0,1): spline_p(x) = c0 + c1 x + c2 x^2 + c3 x^3
//                              + d1 relu(x-0.2)^3 + d2 relu(x-0.6)^3.
// All 9 taps feed every output, so Sum_p c0[p] is a single constant C* used
// as the accumulator init. Each (pixel, output) contribution is 6 chained
// FFMAs against per-pixel features (x, x^2, x^3, R1, R2, silu(x)).
// No inline asm, no shared memory: ptxas gets full scheduling freedom.

namespace {
constexpr int H  = 256, W  = 256;
constexpr int Ho = 254, Wo = 254;
constexpr int NB = 8;          // GRID_SIZE + SPLINE_ORDER
constexpr int TW = 4, TH = 4;  // per-thread output tile
constexpr int BTX = 32, BTY = 8;  // 256 threads; block covers 128x32 outputs
}

__global__ __launch_bounds__(BTX * BTY, 2)
void kan_conv_kernel(const float* __restrict__ x,
                     const float* __restrict__ bw,
                     const float* __restrict__ sw,
                     float* __restrict__ out)
{
    // ---- prologue: truncated-power coefficients per tap ----
    float c1_[9], c2_[9], c3_[9], d1_[9], d2_[9], bw_[9];
    float cstar = 0.0f;
#pragma unroll
    for (int p = 0; p < 9; ++p) {
        float s_[6];
#pragma unroll
        for (int k = 0; k < 6; ++k) s_[k] = __ldg(&sw[p * NB + 2 + k]);
        bw_[p] = __ldg(&bw[p]);

        const float D0 = (-s_[0] + 3.0f * s_[1] - 3.0f * s_[2] + s_[3]) * (1.0f / 6.0f);
        const float D1 = (-s_[1] + 3.0f * s_[2] - 3.0f * s_[3] + s_[4]) * (1.0f / 6.0f);
        const float D2 = (-s_[2] + 3.0f * s_[3] - 3.0f * s_[4] + s_[5]) * (1.0f / 6.0f);
        const float A  = (s_[0] + 4.0f * s_[1] + s_[2]) * (1.0f / 6.0f);
        const float B  = (s_[2] - s_[0]) * 0.5f;
        const float C  = (s_[0] - 2.0f * s_[1] + s_[2]) * 0.5f;

        cstar += A + 0.5f * B + 0.25f * C + 0.125f * D0;
        c1_[p] = 2.5f * B + 2.5f * C + 1.875f * D0;
        c2_[p] = 6.25f * C + 9.375f * D0;
        c3_[p] = 15.625f * D0;
        d1_[p] = 15.625f * (D1 - D0);
        d2_[p] = 15.625f * (D2 - D1);
    }

    const int batch = blockIdx.z;
    const int oc0 = (blockIdx.x * BTX + threadIdx.x) * TW;
    const int or0 = (blockIdx.y * BTY + threadIdx.y) * TH;
    const float* __restrict__ xb = x + batch * H * W;

    float acc[TH][TW];
#pragma unroll
    for (int i = 0; i < TH; ++i)
#pragma unroll
        for (int j = 0; j < TW; ++j) acc[i][j] = cstar;

    const bool fastcols = (oc0 + TW + 2 <= W);   // vector loads fully in-row

#pragma unroll
    for (int r = 0; r < TH + 2; ++r) {
        const int ir = min(or0 + r, H - 1);
        const float* __restrict__ xrow = xb + ir * W;

        float px[TW + 2];
        if (fastcols) {
            const float4 v4 = *reinterpret_cast<const float4*>(xrow + oc0);
            const float2 v2 = *reinterpret_cast<const float2*>(xrow + oc0 + 4);
            px[0] = v4.x; px[1] = v4.y; px[2] = v4.z; px[3] = v4.w;
            px[4] = v2.x; px[5] = v2.y;
        } else {
#pragma unroll
            for (int cc = 0; cc < TW + 2; ++cc)
                px[cc] = __ldg(&xrow[min(oc0 + cc, W - 1)]);
        }

#pragma unroll
        for (int cc = 0; cc < TW + 2; ++cc) {
            const float xv = px[cc];

            // --- per-pixel features (no interval logic) ---
            const float x2 = xv * xv;
            const float x3 = x2 * xv;
            const float r1 = fmaxf(xv - 0.2f, 0.0f);
            const float r2 = fmaxf(xv - 0.6f, 0.0f);
            const float R1 = r1 * r1 * r1;
            const float R2 = r2 * r2 * r2;
            const float e  = __expf(-xv);
            const float s  = __fdividef(xv, 1.0f + e);  // silu(x)

            // --- accumulate: 6 FFMA per (pixel, output) ---
#pragma unroll
            for (int orr = 0; orr < TH; ++orr) {
                const int a = r - orr;
                if (a < 0 || a > 2) continue;
#pragma unroll
                for (int occ = 0; occ < TW; ++occ) {
                    const int b = cc - occ;
                    if (b < 0 || b > 2) continue;
                    const int p = a * 3 + b;
                    float v = fmaf(s,  bw_[p], acc[orr][occ]);
                    v = fmaf(xv, c1_[p], v);
                    v = fmaf(x2, c2_[p], v);
                    v = fmaf(x3, c3_[p], v);
                    v = fmaf(R1, d1_[p], v);
                    v = fmaf(R2, d2_[p], v);
                    acc[orr][occ] = v;
                }
            }
        }
    }

    float* __restrict__ ob = out + batch * Ho * Wo;
#pragma unroll
    for (int orr = 0; orr < TH; ++orr) {
        const int oh = or0 + orr;
        if (oh >= Ho) continue;
        if (oc0 + TW <= Wo) {
            // oh*Wo + oc0 is even (Wo=254 even, oc0 mult of 4) -> 8B aligned.
            float* rowp = ob + oh * Wo + oc0;
            *reinterpret_cast<float2*>(rowp)     = make_float2(acc[orr][0], acc[orr][1]);
            *reinterpret_cast<float2*>(rowp + 2) = make_float2(acc[orr][2], acc[orr][3]);
        } else {
#pragma unroll
            for (int occ = 0; occ < TW; ++occ) {
                const int ow = oc0 + occ;
                if (ow < Wo) ob[oh * Wo + ow] = acc[orr][occ];
            }
        }
    }
}

extern "C" void kernel_launch(void* const* d_in, const int* in_sizes, int n_in,
                              void* d_out, int out_size)
{
    const float* x  = (const float*)d_in[0];
    const float* bw = (const float*)d_in[1];
    const float* sw = (const float*)d_in[2];
    float* out = (float*)d_out;

    dim3 block(BTX, BTY);
    dim3 grid((Wo + BTX * TW - 1) / (BTX * TW),   // 2
              (Ho + BTY * TH - 1) / (BTY * TH),   // 8
              32);
    kan_conv_kernel<<<grid, block>>>(x, bw, sw, out);
}

// round 8
// speedup vs baseline: 1.3304x; 1.1685x over previous
#include <cuda_runtime.h>

// KAN 3x3 convolution — fully polynomialized form.
// x: (32, 256, 256) f32 in [0,1), base_weight: (3,3), spline_weight: (3,3,8)
// out: (32, 254, 254) f32
//
// For x in [0,1): spline_p(x) = c0 + c1 x + c2 x^2 + c3 x^3
//                              + d1 relu(x-0.2)^3 + d2 relu(x-0.6)^3
// and silu(x) is replaced by its Chebyshev cubic on [0,1]
// (max abs err ~1.3e-4, far inside the 1e-3 rel-err budget), so silu*bw
// folds into the polynomial: per (pixel, output) contribution is just
//   c1' x + c2' x^2 + c3' x^3 + d1 R1 + d2 R2      (5 FFMA)
// with all constant terms collapsed into one accumulator-init constant C*.
// No exp/div/MUFU, fewer coefficient registers -> no spills.

namespace {
constexpr int H  = 256, W  = 256;
constexpr int Ho = 254, Wo = 254;
constexpr int NB = 8;          // GRID_SIZE + SPLINE_ORDER
constexpr int TW = 4, TH = 4;  // per-thread output tile
constexpr int BTX = 32, BTY = 8;  // 256 threads; block covers 128x32 outputs

// Chebyshev cubic fit of silu on [0,1]
constexpr float Q0 = 0.0001204f;
constexpr float Q1 = 0.496111f;
constexpr float Q2 = 0.270337f;
constexpr float Q3 = -0.035467f;
}

__global__ __launch_bounds__(BTX * BTY, 2)
void kan_conv_kernel(const float* __restrict__ x,
                     const float* __restrict__ bw,
                     const float* __restrict__ sw,
                     float* __restrict__ out)
{
    // ---- prologue: folded polynomial coefficients per tap ----
    float c1_[9], c2_[9], c3_[9], d1_[9], d2_[9];
    float cstar = 0.0f;
#pragma unroll
    for (int p = 0; p < 9; ++p) {
        float s_[6];
#pragma unroll
        for (int k = 0; k < 6; ++k) s_[k] = __ldg(&sw[p * NB + 2 + k]);
        const float bwp = __ldg(&bw[p]);

        const float D0 = (-s_[0] + 3.0f * s_[1] - 3.0f * s_[2] + s_[3]) * (1.0f / 6.0f);
        const float D1 = (-s_[1] + 3.0f * s_[2] - 3.0f * s_[3] + s_[4]) * (1.0f / 6.0f);
        const float D2 = (-s_[2] + 3.0f * s_[3] - 3.0f * s_[4] + s_[5]) * (1.0f / 6.0f);
        const float A  = (s_[0] + 4.0f * s_[1] + s_[2]) * (1.0f / 6.0f);
        const float B  = (s_[2] - s_[0]) * 0.5f;
        const float C  = (s_[0] - 2.0f * s_[1] + s_[2]) * 0.5f;

        cstar += A + 0.5f * B + 0.25f * C + 0.125f * D0 + bwp * Q0;
        c1_[p] = 2.5f * B + 2.5f * C + 1.875f * D0 + bwp * Q1;
        c2_[p] = 6.25f * C + 9.375f * D0 + bwp * Q2;
        c3_[p] = 15.625f * D0 + bwp * Q3;
        d1_[p] = 15.625f * (D1 - D0);
        d2_[p] = 15.625f * (D2 - D1);
    }

    const int batch = blockIdx.z;
    const int oc0 = (blockIdx.x * BTX + threadIdx.x) * TW;
    const int or0 = (blockIdx.y * BTY + threadIdx.y) * TH;
    const float* __restrict__ xb = x + batch * H * W;

    float acc[TH][TW];
#pragma unroll
    for (int i = 0; i < TH; ++i)
#pragma unroll
        for (int j = 0; j < TW; ++j) acc[i][j] = cstar;

    const bool fastcols = (oc0 + TW + 2 <= W);   // vector loads fully in-row

#pragma unroll
    for (int r = 0; r < TH + 2; ++r) {
        const int ir = min(or0 + r, H - 1);
        const float* __restrict__ xrow = xb + ir * W;

        float px[TW + 2];
        if (fastcols) {
            const float4 v4 = *reinterpret_cast<const float4*>(xrow + oc0);
            const float2 v2 = *reinterpret_cast<const float2*>(xrow + oc0 + 4);
            px[0] = v4.x; px[1] = v4.y; px[2] = v4.z; px[3] = v4.w;
            px[4] = v2.x; px[5] = v2.y;
        } else {
#pragma unroll
            for (int cc = 0; cc < TW + 2; ++cc)
                px[cc] = __ldg(&xrow[min(oc0 + cc, W - 1)]);
        }

#pragma unroll
        for (int cc = 0; cc < TW + 2; ++cc) {
            const float xv = px[cc];

            // --- per-pixel features: 8 cheap ops, no MUFU ---
            const float x2 = xv * xv;
            const float x3 = x2 * xv;
            const float r1 = fmaxf(xv - 0.2f, 0.0f);
            const float r2 = fmaxf(xv - 0.6f, 0.0f);
            const float R1 = (r1 * r1) * r1;
            const float R2 = (r2 * r2) * r2;

            // --- accumulate: 5 FFMA per (pixel, output) ---
#pragma unroll
            for (int orr = 0; orr < TH; ++orr) {
                const int a = r - orr;
                if (a < 0 || a > 2) continue;
#pragma unroll
                for (int occ = 0; occ < TW; ++occ) {
                    const int b = cc - occ;
                    if (b < 0 || b > 2) continue;
                    const int p = a * 3 + b;
                    float v = fmaf(xv, c1_[p], acc[orr][occ]);
                    v = fmaf(x2, c2_[p], v);
                    v = fmaf(x3, c3_[p], v);
                    v = fmaf(R1, d1_[p], v);
                    v = fmaf(R2, d2_[p], v);
                    acc[orr][occ] = v;
                }
            }
        }
    }

    float* __restrict__ ob = out + batch * Ho * Wo;
#pragma unroll
    for (int orr = 0; orr < TH; ++orr) {
        const int oh = or0 + orr;
        if (oh >= Ho) continue;
        if (oc0 + TW <= Wo) {
            // oh*Wo + oc0 is even (Wo=254 even, oc0 mult of 4) -> 8B aligned.
            float* rowp = ob + oh * Wo + oc0;
            *reinterpret_cast<float2*>(rowp)     = make_float2(acc[orr][0], acc[orr][1]);
            *reinterpret_cast<float2*>(rowp + 2) = make_float2(acc[orr][2], acc[orr][3]);
        } else {
#pragma unroll
            for (int occ = 0; occ < TW; ++occ) {
                const int ow = oc0 + occ;
                if (ow < Wo) ob[oh * Wo + ow] = acc[orr][occ];
            }
        }
    }
}

extern "C" void kernel_launch(void* const* d_in, const int* in_sizes, int n_in,
                              void* d_out, int out_size)
{
    const float* x  = (const float*)d_in[0];
    const float* bw = (const float*)d_in[1];
    const float* sw = (const float*)d_in[2];
    float* out = (float*)d_out;

    dim3 block(BTX, BTY);
    dim3 grid((Wo + BTX * TW - 1) / (BTX * TW),   // 2
              (Ho + BTY * TH - 1) / (BTY * TH),   // 8
              32);
    kan_conv_kernel<<<grid, block>>>(x, bw, sw, out);
}